// round 1
// baseline (speedup 1.0000x reference)
#include <cuda_runtime.h>
#include <cuda_bf16.h>
#include <math.h>

// Problem shapes (fixed by the dataset)
#define B_   8
#define HW_  32
#define T_   31
#define NF_  256
#define E_   512
#define M_   2048
#define H_   8
#define DH_  64

#define ROWS_Q   (B_ * NF_)            // 2048
#define ROWS_KV  (B_ * T_ * NF_)       // 63488

// ---------------- static scratch (allocation-free rule) ----------------
__device__ float g_qln [ (size_t)ROWS_Q  * E_ ];
__device__ float g_q   [ (size_t)ROWS_Q  * E_ ];
__device__ float g_kvln[ (size_t)ROWS_KV * E_ ];
__device__ float g_k   [ (size_t)ROWS_KV * E_ ];
__device__ float g_v   [ (size_t)ROWS_KV * E_ ];
__device__ float g_t1  [ (size_t)ROWS_KV * E_ ];
__device__ float g_t2  [ (size_t)ROWS_KV * E_ ];
__device__ float g_hid [ (size_t)ROWS_KV * M_ ];

// ---------------- helpers ----------------
__device__ __forceinline__ float gelu_exact(float x) {
    return 0.5f * x * (1.0f + erff(x * 0.70710678118654752f));
}

__device__ __forceinline__ float blk_sum(float v, float* sb) {
    #pragma unroll
    for (int o = 16; o; o >>= 1) v += __shfl_xor_sync(0xffffffffu, v, o);
    if ((threadIdx.x & 31) == 0) sb[threadIdx.x >> 5] = v;
    __syncthreads();
    float r = sb[0] + sb[1] + sb[2] + sb[3];
    __syncthreads();
    return r;
}

// ---------------- LN of input, split into q-path (t==0) and kv-path ----------------
// grid = B*HW*NF blocks of 128 threads; each block = one 512-wide row.
__global__ void __launch_bounds__(128) ln_in_kernel(
    const float* __restrict__ X,
    const float* __restrict__ gq,  const float* __restrict__ bq,
    const float* __restrict__ gkv, const float* __restrict__ bkv,
    float* __restrict__ out_q, float* __restrict__ out_kv)
{
    __shared__ float sb[4];
    int r = blockIdx.x;                       // = (b*32 + t)*256 + n
    int b = r >> 13;
    int t = (r >> 8) & 31;
    int n = r & 255;
    int c = threadIdx.x * 4;

    const float* x = X + (size_t)r * E_ + c;
    float4 xv = *(const float4*)x;
    float s = xv.x + xv.y + xv.z + xv.w;
    float mean = blk_sum(s, sb) * (1.0f / E_);
    float dx0 = xv.x - mean, dx1 = xv.y - mean, dx2 = xv.z - mean, dx3 = xv.w - mean;
    float sq = dx0*dx0 + dx1*dx1 + dx2*dx2 + dx3*dx3;
    float var = blk_sum(sq, sb) * (1.0f / E_);
    float rs = rsqrtf(var + 1e-6f);

    const float *g, *be; float* dst;
    if (t == 0) { g = gq;  be = bq;  dst = out_q  + ((size_t)(b * NF_ + n)) * E_; }
    else        { g = gkv; be = bkv; dst = out_kv + ((size_t)((b * T_ + (t - 1)) * NF_ + n)) * E_; }

    float4 gg = *(const float4*)(g + c);
    float4 bb = *(const float4*)(be + c);
    float4 y;
    y.x = dx0 * rs * gg.x + bb.x;
    y.y = dx1 * rs * gg.y + bb.y;
    y.z = dx2 * rs * gg.z + bb.z;
    y.w = dx3 * rs * gg.w + bb.w;
    *(float4*)(dst + c) = y;
}

// ---------------- fused double LayerNorm: Y = LN2(LN1(X)) ----------------
__global__ void __launch_bounds__(128) dual_ln_kernel(
    const float* __restrict__ X,
    const float* __restrict__ g1, const float* __restrict__ b1,
    const float* __restrict__ g2, const float* __restrict__ b2,
    float* __restrict__ Y)
{
    __shared__ float sb[4];
    size_t r = blockIdx.x;
    int c = threadIdx.x * 4;
    float4 xv = *(const float4*)(X + r * E_ + c);

    float s = xv.x + xv.y + xv.z + xv.w;
    float mean = blk_sum(s, sb) * (1.0f / E_);
    float d0 = xv.x - mean, d1 = xv.y - mean, d2 = xv.z - mean, d3 = xv.w - mean;
    float var = blk_sum(d0*d0 + d1*d1 + d2*d2 + d3*d3, sb) * (1.0f / E_);
    float rs = rsqrtf(var + 1e-6f);

    float4 gg = *(const float4*)(g1 + c);
    float4 bb = *(const float4*)(b1 + c);
    float y0 = d0 * rs * gg.x + bb.x;
    float y1 = d1 * rs * gg.y + bb.y;
    float y2 = d2 * rs * gg.z + bb.z;
    float y3 = d3 * rs * gg.w + bb.w;

    float s2 = y0 + y1 + y2 + y3;
    float mean2 = blk_sum(s2, sb) * (1.0f / E_);
    float e0 = y0 - mean2, e1 = y1 - mean2, e2 = y2 - mean2, e3 = y3 - mean2;
    float var2 = blk_sum(e0*e0 + e1*e1 + e2*e2 + e3*e3, sb) * (1.0f / E_);
    float rs2 = rsqrtf(var2 + 1e-6f);

    float4 gg2 = *(const float4*)(g2 + c);
    float4 bb2 = *(const float4*)(b2 + c);
    float4 out;
    out.x = e0 * rs2 * gg2.x + bb2.x;
    out.y = e1 * rs2 * gg2.y + bb2.y;
    out.z = e2 * rs2 * gg2.z + bb2.z;
    out.w = e3 * rs2 * gg2.w + bb2.w;
    *(float4*)(Y + r * E_ + c) = out;
}

// ---------------- SGEMM: C = epi(A @ B + bias [+ res]) ----------------
// A: MxK row-major, B: KxN row-major. M%128==0, N%128==0, K%8==0.
// 128x128 tile, BK=8, 256 threads, 8x8 accum per thread.
template<bool DO_GELU, bool DO_RES>
__global__ void __launch_bounds__(256) sgemm_k(
    const float* __restrict__ A, const float* __restrict__ B,
    const float* __restrict__ bias, const float* __restrict__ res,
    float* __restrict__ C, int M, int N, int K)
{
    __shared__ float As[8][128];
    __shared__ float Bs[8][128];

    const int tid = threadIdx.x;
    const int tx = tid & 15;           // 0..15 -> col group
    const int ty = tid >> 4;           // 0..15 -> row group
    const int brow = blockIdx.y * 128;
    const int bcol = blockIdx.x * 128;

    const int arow = tid >> 1;         // 0..127
    const int acol = (tid & 1) * 4;    // 0 or 4
    const int bkr  = tid >> 5;         // 0..7
    const int bc4  = (tid & 31) * 4;   // 0..124

    const float* Aptr = A + (size_t)(brow + arow) * K + acol;
    const float* Bptr = B + (size_t)bkr * N + bcol + bc4;

    float acc[8][8];
    #pragma unroll
    for (int i = 0; i < 8; i++)
        #pragma unroll
        for (int j = 0; j < 8; j++) acc[i][j] = 0.0f;

    for (int k0 = 0; k0 < K; k0 += 8) {
        float4 a4 = *(const float4*)(Aptr + k0);
        As[acol + 0][arow] = a4.x;
        As[acol + 1][arow] = a4.y;
        As[acol + 2][arow] = a4.z;
        As[acol + 3][arow] = a4.w;
        *(float4*)&Bs[bkr][bc4] = *(const float4*)(Bptr + (size_t)k0 * N);
        __syncthreads();

        #pragma unroll
        for (int kk = 0; kk < 8; ++kk) {
            float ra[8], rb[8];
            *(float4*)&ra[0] = *(const float4*)&As[kk][ty * 8];
            *(float4*)&ra[4] = *(const float4*)&As[kk][ty * 8 + 4];
            *(float4*)&rb[0] = *(const float4*)&Bs[kk][tx * 8];
            *(float4*)&rb[4] = *(const float4*)&Bs[kk][tx * 8 + 4];
            #pragma unroll
            for (int i = 0; i < 8; i++)
                #pragma unroll
                for (int j = 0; j < 8; j++)
                    acc[i][j] = fmaf(ra[i], rb[j], acc[i][j]);
        }
        __syncthreads();
    }

    // epilogue
    float bb[8];
    *(float4*)&bb[0] = *(const float4*)(bias + bcol + tx * 8);
    *(float4*)&bb[4] = *(const float4*)(bias + bcol + tx * 8 + 4);

    #pragma unroll
    for (int i = 0; i < 8; i++) {
        int row = brow + ty * 8 + i;
        size_t off = (size_t)row * N + bcol + tx * 8;
        #pragma unroll
        for (int j0 = 0; j0 < 8; j0 += 4) {
            float v0 = acc[i][j0 + 0] + bb[j0 + 0];
            float v1 = acc[i][j0 + 1] + bb[j0 + 1];
            float v2 = acc[i][j0 + 2] + bb[j0 + 2];
            float v3 = acc[i][j0 + 3] + bb[j0 + 3];
            if (DO_RES) {
                float4 rr = *(const float4*)(res + off + j0);
                v0 += rr.x; v1 += rr.y; v2 += rr.z; v3 += rr.w;
            }
            if (DO_GELU) {
                v0 = gelu_exact(v0); v1 = gelu_exact(v1);
                v2 = gelu_exact(v2); v3 = gelu_exact(v3);
            }
            float4 out; out.x = v0; out.y = v1; out.z = v2; out.w = v3;
            *(float4*)(C + off + j0) = out;
        }
    }
}

// ---------------- fused attention ----------------
// 1 block per (b,t,h), 256 threads, thread = query row n. q and o in registers,
// K/V streamed through smem in 16-key chunks, online softmax.
__global__ void __launch_bounds__(256, 1) attn_kernel(
    const float* __restrict__ Q, const float* __restrict__ Kg,
    const float* __restrict__ Vg, float* __restrict__ O)
{
    __shared__ float kbuf[16][64];
    __shared__ float vbuf[16][64];

    int idx = blockIdx.x;
    int h = idx % H_;
    int bt = idx / H_;                 // b*T + t
    int b = bt / T_;

    int n = threadIdx.x;
    const float* qrow = Q + ((size_t)(b * NF_ + n)) * E_ + h * DH_;
    float q[64];
    #pragma unroll
    for (int i = 0; i < 16; i++) *(float4*)&q[i * 4] = *(const float4*)&qrow[i * 4];

    float o[64];
    #pragma unroll
    for (int i = 0; i < 64; i++) o[i] = 0.0f;
    float mmax = -3.4e38f, l = 0.0f;

    size_t base = (size_t)bt * NF_ * E_ + h * DH_;
    const int jr = threadIdx.x >> 4;          // 0..15
    const int dc = (threadIdx.x & 15) * 4;    // 0..60

    for (int j0 = 0; j0 < NF_; j0 += 16) {
        __syncthreads();
        *(float4*)&kbuf[jr][dc] = *(const float4*)(Kg + base + (size_t)(j0 + jr) * E_ + dc);
        *(float4*)&vbuf[jr][dc] = *(const float4*)(Vg + base + (size_t)(j0 + jr) * E_ + dc);
        __syncthreads();

        #pragma unroll
        for (int jj = 0; jj < 16; jj++) {
            float s = 0.0f;
            #pragma unroll
            for (int d = 0; d < 64; d++) s = fmaf(q[d], kbuf[jj][d], s);
            s *= 0.125f;                              // 1/sqrt(64)
            float mnew = fmaxf(mmax, s);
            float alpha = __expf(mmax - mnew);
            float p = __expf(s - mnew);
            l = l * alpha + p;
            #pragma unroll
            for (int d = 0; d < 64; d++) o[d] = o[d] * alpha + p * vbuf[jj][d];
            mmax = mnew;
        }
    }

    float inv = 1.0f / l;
    float* orow = O + ((size_t)bt * NF_ + n) * E_ + h * DH_;
    #pragma unroll
    for (int i = 0; i < 16; i++) {
        float4 out;
        out.x = o[i * 4 + 0] * inv;
        out.y = o[i * 4 + 1] * inv;
        out.z = o[i * 4 + 2] * inv;
        out.w = o[i * 4 + 3] * inv;
        *(float4*)&orow[i * 4] = out;
    }
}

// ---------------- host ----------------
extern "C" void kernel_launch(void* const* d_in, const int* in_sizes, int n_in,
                              void* d_out, int out_size)
{
    const float* inputs  = (const float*)d_in[0];
    const float* wq      = (const float*)d_in[1];
    const float* wk      = (const float*)d_in[2];
    const float* wv      = (const float*)d_in[3];
    const float* bq      = (const float*)d_in[4];
    const float* bk      = (const float*)d_in[5];
    const float* bv      = (const float*)d_in[6];
    const float* wo      = (const float*)d_in[7];
    const float* bo      = (const float*)d_in[8];
    const float* lnq_g   = (const float*)d_in[9];
    const float* lnq_b   = (const float*)d_in[10];
    const float* lnkv_g  = (const float*)d_in[11];
    const float* lnkv_b  = (const float*)d_in[12];
    const float* mlpq_w1 = (const float*)d_in[13];
    const float* mlpq_b1 = (const float*)d_in[14];
    const float* mlpq_w2 = (const float*)d_in[15];
    const float* mlpq_b2 = (const float*)d_in[16];
    const float* resln_g = (const float*)d_in[17];
    const float* resln_b = (const float*)d_in[18];
    const float* ln2_g   = (const float*)d_in[19];
    const float* ln2_b   = (const float*)d_in[20];
    const float* mlp_w1  = (const float*)d_in[21];
    const float* mlp_b1  = (const float*)d_in[22];
    const float* mlp_w2  = (const float*)d_in[23];
    const float* mlp_b2  = (const float*)d_in[24];
    float* out = (float*)d_out;

    float *qln, *q, *kvln, *k, *v, *t1, *t2, *hid;
    cudaGetSymbolAddress((void**)&qln,  g_qln);
    cudaGetSymbolAddress((void**)&q,    g_q);
    cudaGetSymbolAddress((void**)&kvln, g_kvln);
    cudaGetSymbolAddress((void**)&k,    g_k);
    cudaGetSymbolAddress((void**)&v,    g_v);
    cudaGetSymbolAddress((void**)&t1,   g_t1);
    cudaGetSymbolAddress((void**)&t2,   g_t2);
    cudaGetSymbolAddress((void**)&hid,  g_hid);

    // 1) LayerNorms of the input, routed to q / kv paths
    ln_in_kernel<<<B_ * HW_ * NF_, 128>>>(inputs, lnq_g, lnq_b, lnkv_g, lnkv_b, qln, kvln);

    // 2) projections
    sgemm_k<false,false><<<dim3(E_/128, ROWS_Q/128),  256>>>(qln,  wq, bq, nullptr, q, ROWS_Q,  E_, E_);
    sgemm_k<false,false><<<dim3(E_/128, ROWS_KV/128), 256>>>(kvln, wk, bk, nullptr, k, ROWS_KV, E_, E_);
    sgemm_k<false,false><<<dim3(E_/128, ROWS_KV/128), 256>>>(kvln, wv, bv, nullptr, v, ROWS_KV, E_, E_);

    // 3) attention -> t1 (layout (b,t,n, h*64+d))
    attn_kernel<<<B_ * T_ * H_, 256>>>(q, k, v, t1);

    // 4) out projection -> t2
    sgemm_k<false,false><<<dim3(E_/128, ROWS_KV/128), 256>>>(t1, wo, bo, nullptr, t2, ROWS_KV, E_, E_);

    // 5) mlp_q: t2 -> hid (GELU) -> t1 (+ residual kvln), pre-LN
    sgemm_k<true, false><<<dim3(M_/128, ROWS_KV/128), 256>>>(t2, mlpq_w1, mlpq_b1, nullptr, hid, ROWS_KV, M_, E_);
    sgemm_k<false,true ><<<dim3(E_/128, ROWS_KV/128), 256>>>(hid, mlpq_w2, mlpq_b2, kvln,   t1,  ROWS_KV, E_, M_);

    // 6) res_ln then ln_2 fused: t1 -> t2
    dual_ln_kernel<<<ROWS_KV, 128>>>(t1, resln_g, resln_b, ln2_g, ln2_b, t2);

    // 7) final MLP: t2 -> hid (GELU) -> out
    sgemm_k<true, false><<<dim3(M_/128, ROWS_KV/128), 256>>>(t2,  mlp_w1, mlp_b1, nullptr, hid, ROWS_KV, M_, E_);
    sgemm_k<false,false><<<dim3(E_/128, ROWS_KV/128), 256>>>(hid, mlp_w2, mlp_b2, nullptr, out, ROWS_KV, E_, M_);
}

// round 2
// speedup vs baseline: 2.4489x; 2.4489x over previous
#include <cuda_runtime.h>
#include <cuda_bf16.h>
#include <math.h>
#include <stdint.h>

// Problem shapes (fixed by the dataset)
#define B_   8
#define HW_  32
#define T_   31
#define NF_  256
#define E_   512
#define M_   2048
#define H_   8
#define DH_  64

#define ROWS_Q   (B_ * NF_)            // 2048
#define ROWS_KV  (B_ * T_ * NF_)       // 63488

// ---------------- static scratch (allocation-free rule) ----------------
__device__ float g_qln [ (size_t)ROWS_Q  * E_ ];
__device__ float g_q   [ (size_t)ROWS_Q  * E_ ];
__device__ float g_kvln[ (size_t)ROWS_KV * E_ ];
__device__ float g_k   [ (size_t)ROWS_KV * E_ ];
__device__ float g_v   [ (size_t)ROWS_KV * E_ ];
__device__ float g_t1  [ (size_t)ROWS_KV * E_ ];
__device__ float g_t2  [ (size_t)ROWS_KV * E_ ];
__device__ float g_hid [ (size_t)ROWS_KV * M_ ];

// ---------------- helpers ----------------
__device__ __forceinline__ float gelu_exact(float x) {
    return 0.5f * x * (1.0f + erff(x * 0.70710678118654752f));
}

__device__ __forceinline__ uint32_t f2tf(float x) {
    uint32_t r;
    asm("cvt.rna.tf32.f32 %0, %1;" : "=r"(r) : "f"(x));
    return r;
}

__device__ __forceinline__ void mma_tf32(float* d, const uint32_t* a, const uint32_t* b) {
    asm volatile(
        "mma.sync.aligned.m16n8k8.row.col.f32.tf32.tf32.f32 "
        "{%0,%1,%2,%3}, {%4,%5,%6,%7}, {%8,%9}, {%0,%1,%2,%3};"
        : "+f"(d[0]), "+f"(d[1]), "+f"(d[2]), "+f"(d[3])
        : "r"(a[0]), "r"(a[1]), "r"(a[2]), "r"(a[3]), "r"(b[0]), "r"(b[1]));
}

__device__ __forceinline__ float blk_sum(float v, float* sb) {
    #pragma unroll
    for (int o = 16; o; o >>= 1) v += __shfl_xor_sync(0xffffffffu, v, o);
    if ((threadIdx.x & 31) == 0) sb[threadIdx.x >> 5] = v;
    __syncthreads();
    float r = sb[0] + sb[1] + sb[2] + sb[3];
    __syncthreads();
    return r;
}

// ---------------- LN of input, split into q-path (t==0) and kv-path ----------------
__global__ void __launch_bounds__(128) ln_in_kernel(
    const float* __restrict__ X,
    const float* __restrict__ gq,  const float* __restrict__ bq,
    const float* __restrict__ gkv, const float* __restrict__ bkv,
    float* __restrict__ out_q, float* __restrict__ out_kv)
{
    __shared__ float sb[4];
    int r = blockIdx.x;                       // = (b*32 + t)*256 + n
    int b = r >> 13;
    int t = (r >> 8) & 31;
    int n = r & 255;
    int c = threadIdx.x * 4;

    const float* x = X + (size_t)r * E_ + c;
    float4 xv = *(const float4*)x;
    float s = xv.x + xv.y + xv.z + xv.w;
    float mean = blk_sum(s, sb) * (1.0f / E_);
    float dx0 = xv.x - mean, dx1 = xv.y - mean, dx2 = xv.z - mean, dx3 = xv.w - mean;
    float sq = dx0*dx0 + dx1*dx1 + dx2*dx2 + dx3*dx3;
    float var = blk_sum(sq, sb) * (1.0f / E_);
    float rs = rsqrtf(var + 1e-6f);

    const float *g, *be; float* dst;
    if (t == 0) { g = gq;  be = bq;  dst = out_q  + ((size_t)(b * NF_ + n)) * E_; }
    else        { g = gkv; be = bkv; dst = out_kv + ((size_t)((b * T_ + (t - 1)) * NF_ + n)) * E_; }

    float4 gg = *(const float4*)(g + c);
    float4 bb = *(const float4*)(be + c);
    float4 y;
    y.x = dx0 * rs * gg.x + bb.x;
    y.y = dx1 * rs * gg.y + bb.y;
    y.z = dx2 * rs * gg.z + bb.z;
    y.w = dx3 * rs * gg.w + bb.w;
    *(float4*)(dst + c) = y;
}

// ---------------- fused double LayerNorm: Y = LN2(LN1(X)) ----------------
__global__ void __launch_bounds__(128) dual_ln_kernel(
    const float* __restrict__ X,
    const float* __restrict__ g1, const float* __restrict__ b1,
    const float* __restrict__ g2, const float* __restrict__ b2,
    float* __restrict__ Y)
{
    __shared__ float sb[4];
    size_t r = blockIdx.x;
    int c = threadIdx.x * 4;
    float4 xv = *(const float4*)(X + r * E_ + c);

    float s = xv.x + xv.y + xv.z + xv.w;
    float mean = blk_sum(s, sb) * (1.0f / E_);
    float d0 = xv.x - mean, d1 = xv.y - mean, d2 = xv.z - mean, d3 = xv.w - mean;
    float var = blk_sum(d0*d0 + d1*d1 + d2*d2 + d3*d3, sb) * (1.0f / E_);
    float rs = rsqrtf(var + 1e-6f);

    float4 gg = *(const float4*)(g1 + c);
    float4 bb = *(const float4*)(b1 + c);
    float y0 = d0 * rs * gg.x + bb.x;
    float y1 = d1 * rs * gg.y + bb.y;
    float y2 = d2 * rs * gg.z + bb.z;
    float y3 = d3 * rs * gg.w + bb.w;

    float s2 = y0 + y1 + y2 + y3;
    float mean2 = blk_sum(s2, sb) * (1.0f / E_);
    float e0 = y0 - mean2, e1 = y1 - mean2, e2 = y2 - mean2, e3 = y3 - mean2;
    float var2 = blk_sum(e0*e0 + e1*e1 + e2*e2 + e3*e3, sb) * (1.0f / E_);
    float rs2 = rsqrtf(var2 + 1e-6f);

    float4 gg2 = *(const float4*)(g2 + c);
    float4 bb2 = *(const float4*)(b2 + c);
    float4 out;
    out.x = e0 * rs2 * gg2.x + bb2.x;
    out.y = e1 * rs2 * gg2.y + bb2.y;
    out.z = e2 * rs2 * gg2.z + bb2.z;
    out.w = e3 * rs2 * gg2.w + bb2.w;
    *(float4*)(Y + r * E_ + c) = out;
}

// ---------------- tf32 tensor-core GEMM: C = epi(A @ B + bias [+ res]) ----------------
// A: MxK row-major fp32, B: KxN row-major fp32. M%128==0, N%128==0, K%16==0.
// 128x128x16 tile, 256 threads = 8 warps (2x4), warp tile 64x32 (4x4 m16n8k8).
#define BKT 16
#define LDSW 136   // 128 + 8 pad: keeps 16B STS alignment, conflict-free frag LDS

template<bool DO_GELU, bool DO_RES>
__global__ void __launch_bounds__(256) tgemm_k(
    const float* __restrict__ A, const float* __restrict__ B,
    const float* __restrict__ bias, const float* __restrict__ res,
    float* __restrict__ C, int M, int N, int K)
{
    __shared__ uint32_t As[2][BKT][LDSW];
    __shared__ uint32_t Bs[2][BKT][LDSW];

    const int tid  = threadIdx.x;
    const int warp = tid >> 5, lane = tid & 31;
    const int wr = warp >> 2, wc = warp & 3;       // 2 x 4 warp grid
    const int group = lane >> 2, quad = lane & 3;
    const int mb = wr * 64, nb = wc * 32;
    const int brow = blockIdx.y * 128;
    const int bcol = blockIdx.x * 128;

    float acc[4][4][4];
    #pragma unroll
    for (int mi = 0; mi < 4; mi++)
        #pragma unroll
        for (int ni = 0; ni < 4; ni++)
            #pragma unroll
            for (int r = 0; r < 4; r++) acc[mi][ni][r] = 0.0f;

    // gmem staging registers
    float4 aR[2], bR[2];

    // A tile: 128 rows x 16 k = 512 float4 (4 float4 per row)
    const int a_r0  = tid >> 2;          // rows for idx=tid, idx2=tid+256 -> +64
    const int a_c0  = (tid & 3) * 4;
    // B tile: 16 k x 128 n = 512 float4 (32 float4 per row)
    const int b_k0  = tid >> 5;          // k for idx=tid (0..7), +8 for idx2
    const int b_n0  = (tid & 31) * 4;

    const int nkt = K / BKT;

    auto ldg = [&](int kt) {
        aR[0] = *(const float4*)(A + (size_t)(brow + a_r0)      * K + kt * BKT + a_c0);
        aR[1] = *(const float4*)(A + (size_t)(brow + a_r0 + 64) * K + kt * BKT + a_c0);
        bR[0] = *(const float4*)(B + (size_t)(kt * BKT + b_k0)     * N + bcol + b_n0);
        bR[1] = *(const float4*)(B + (size_t)(kt * BKT + b_k0 + 8) * N + bcol + b_n0);
    };
    auto sts = [&](int buf) {
        #pragma unroll
        for (int i = 0; i < 2; i++) {
            float4 a4 = aR[i];
            int r = a_r0 + i * 64;
            As[buf][a_c0 + 0][r] = f2tf(a4.x);
            As[buf][a_c0 + 1][r] = f2tf(a4.y);
            As[buf][a_c0 + 2][r] = f2tf(a4.z);
            As[buf][a_c0 + 3][r] = f2tf(a4.w);
            float4 b4 = bR[i];
            uint4 u;
            u.x = f2tf(b4.x); u.y = f2tf(b4.y); u.z = f2tf(b4.z); u.w = f2tf(b4.w);
            *(uint4*)&Bs[buf][b_k0 + i * 8][b_n0] = u;
        }
    };

    ldg(0);
    sts(0);
    __syncthreads();

    for (int kt = 0; kt < nkt; kt++) {
        const int cur = kt & 1;
        if (kt + 1 < nkt) ldg(kt + 1);

        #pragma unroll
        for (int ks = 0; ks < 2; ks++) {
            uint32_t af[4][4], bf[4][2];
            #pragma unroll
            for (int mi = 0; mi < 4; mi++) {
                int m0 = mb + mi * 16 + group;
                af[mi][0] = As[cur][ks * 8 + quad][m0];
                af[mi][1] = As[cur][ks * 8 + quad][m0 + 8];
                af[mi][2] = As[cur][ks * 8 + quad + 4][m0];
                af[mi][3] = As[cur][ks * 8 + quad + 4][m0 + 8];
            }
            #pragma unroll
            for (int ni = 0; ni < 4; ni++) {
                int n0 = nb + ni * 8 + group;
                bf[ni][0] = Bs[cur][ks * 8 + quad][n0];
                bf[ni][1] = Bs[cur][ks * 8 + quad + 4][n0];
            }
            #pragma unroll
            for (int mi = 0; mi < 4; mi++)
                #pragma unroll
                for (int ni = 0; ni < 4; ni++)
                    mma_tf32(acc[mi][ni], af[mi], bf[ni]);
        }

        if (kt + 1 < nkt) sts(cur ^ 1);
        __syncthreads();
    }

    // ---- epilogue ----
    #pragma unroll
    for (int ni = 0; ni < 4; ni++) {
        int col = bcol + nb + ni * 8 + quad * 2;
        float bb0 = bias[col], bb1 = bias[col + 1];
        #pragma unroll
        for (int mi = 0; mi < 4; mi++) {
            #pragma unroll
            for (int h = 0; h < 2; h++) {
                int row = brow + mb + mi * 16 + group + h * 8;
                size_t off = (size_t)row * N + col;
                float v0 = acc[mi][ni][h * 2 + 0] + bb0;
                float v1 = acc[mi][ni][h * 2 + 1] + bb1;
                if (DO_RES) {
                    float2 rr = *(const float2*)(res + off);
                    v0 += rr.x; v1 += rr.y;
                }
                if (DO_GELU) { v0 = gelu_exact(v0); v1 = gelu_exact(v1); }
                float2 o; o.x = v0; o.y = v1;
                *(float2*)(C + off) = o;
            }
        }
    }
}

// ---------------- fused attention ----------------
__global__ void __launch_bounds__(256, 1) attn_kernel(
    const float* __restrict__ Q, const float* __restrict__ Kg,
    const float* __restrict__ Vg, float* __restrict__ O)
{
    __shared__ float kbuf[16][64];
    __shared__ float vbuf[16][64];

    int idx = blockIdx.x;
    int h = idx % H_;
    int bt = idx / H_;
    int b = bt / T_;

    int n = threadIdx.x;
    const float* qrow = Q + ((size_t)(b * NF_ + n)) * E_ + h * DH_;
    float q[64];
    #pragma unroll
    for (int i = 0; i < 16; i++) *(float4*)&q[i * 4] = *(const float4*)&qrow[i * 4];

    float o[64];
    #pragma unroll
    for (int i = 0; i < 64; i++) o[i] = 0.0f;
    float mmax = -3.4e38f, l = 0.0f;

    size_t base = (size_t)bt * NF_ * E_ + h * DH_;
    const int jr = threadIdx.x >> 4;
    const int dc = (threadIdx.x & 15) * 4;

    for (int j0 = 0; j0 < NF_; j0 += 16) {
        __syncthreads();
        *(float4*)&kbuf[jr][dc] = *(const float4*)(Kg + base + (size_t)(j0 + jr) * E_ + dc);
        *(float4*)&vbuf[jr][dc] = *(const float4*)(Vg + base + (size_t)(j0 + jr) * E_ + dc);
        __syncthreads();

        #pragma unroll
        for (int jj = 0; jj < 16; jj++) {
            float s = 0.0f;
            #pragma unroll
            for (int d = 0; d < 64; d++) s = fmaf(q[d], kbuf[jj][d], s);
            s *= 0.125f;
            float mnew = fmaxf(mmax, s);
            float alpha = __expf(mmax - mnew);
            float p = __expf(s - mnew);
            l = l * alpha + p;
            #pragma unroll
            for (int d = 0; d < 64; d++) o[d] = o[d] * alpha + p * vbuf[jj][d];
            mmax = mnew;
        }
    }

    float inv = 1.0f / l;
    float* orow = O + ((size_t)bt * NF_ + n) * E_ + h * DH_;
    #pragma unroll
    for (int i = 0; i < 16; i++) {
        float4 out;
        out.x = o[i * 4 + 0] * inv;
        out.y = o[i * 4 + 1] * inv;
        out.z = o[i * 4 + 2] * inv;
        out.w = o[i * 4 + 3] * inv;
        *(float4*)&orow[i * 4] = out;
    }
}

// ---------------- host ----------------
extern "C" void kernel_launch(void* const* d_in, const int* in_sizes, int n_in,
                              void* d_out, int out_size)
{
    const float* inputs  = (const float*)d_in[0];
    const float* wq      = (const float*)d_in[1];
    const float* wk      = (const float*)d_in[2];
    const float* wv      = (const float*)d_in[3];
    const float* bq      = (const float*)d_in[4];
    const float* bk      = (const float*)d_in[5];
    const float* bv      = (const float*)d_in[6];
    const float* wo      = (const float*)d_in[7];
    const float* bo      = (const float*)d_in[8];
    const float* lnq_g   = (const float*)d_in[9];
    const float* lnq_b   = (const float*)d_in[10];
    const float* lnkv_g  = (const float*)d_in[11];
    const float* lnkv_b  = (const float*)d_in[12];
    const float* mlpq_w1 = (const float*)d_in[13];
    const float* mlpq_b1 = (const float*)d_in[14];
    const float* mlpq_w2 = (const float*)d_in[15];
    const float* mlpq_b2 = (const float*)d_in[16];
    const float* resln_g = (const float*)d_in[17];
    const float* resln_b = (const float*)d_in[18];
    const float* ln2_g   = (const float*)d_in[19];
    const float* ln2_b   = (const float*)d_in[20];
    const float* mlp_w1  = (const float*)d_in[21];
    const float* mlp_b1  = (const float*)d_in[22];
    const float* mlp_w2  = (const float*)d_in[23];
    const float* mlp_b2  = (const float*)d_in[24];
    float* out = (float*)d_out;

    float *qln, *q, *kvln, *k, *v, *t1, *t2, *hid;
    cudaGetSymbolAddress((void**)&qln,  g_qln);
    cudaGetSymbolAddress((void**)&q,    g_q);
    cudaGetSymbolAddress((void**)&kvln, g_kvln);
    cudaGetSymbolAddress((void**)&k,    g_k);
    cudaGetSymbolAddress((void**)&v,    g_v);
    cudaGetSymbolAddress((void**)&t1,   g_t1);
    cudaGetSymbolAddress((void**)&t2,   g_t2);
    cudaGetSymbolAddress((void**)&hid,  g_hid);

    // 1) LayerNorms of the input, routed to q / kv paths
    ln_in_kernel<<<B_ * HW_ * NF_, 128>>>(inputs, lnq_g, lnq_b, lnkv_g, lnkv_b, qln, kvln);

    // 2) projections (tensor-core tf32)
    tgemm_k<false,false><<<dim3(E_/128, ROWS_Q/128),  256>>>(qln,  wq, bq, nullptr, q, ROWS_Q,  E_, E_);
    tgemm_k<false,false><<<dim3(E_/128, ROWS_KV/128), 256>>>(kvln, wk, bk, nullptr, k, ROWS_KV, E_, E_);
    tgemm_k<false,false><<<dim3(E_/128, ROWS_KV/128), 256>>>(kvln, wv, bv, nullptr, v, ROWS_KV, E_, E_);

    // 3) attention -> t1
    attn_kernel<<<B_ * T_ * H_, 256>>>(q, k, v, t1);

    // 4) out projection -> t2
    tgemm_k<false,false><<<dim3(E_/128, ROWS_KV/128), 256>>>(t1, wo, bo, nullptr, t2, ROWS_KV, E_, E_);

    // 5) mlp_q: t2 -> hid (GELU) -> t1 (+ residual kvln)
    tgemm_k<true, false><<<dim3(M_/128, ROWS_KV/128), 256>>>(t2, mlpq_w1, mlpq_b1, nullptr, hid, ROWS_KV, M_, E_);
    tgemm_k<false,true ><<<dim3(E_/128, ROWS_KV/128), 256>>>(hid, mlpq_w2, mlpq_b2, kvln,   t1,  ROWS_KV, E_, M_);

    // 6) res_ln then ln_2 fused: t1 -> t2
    dual_ln_kernel<<<ROWS_KV, 128>>>(t1, resln_g, resln_b, ln2_g, ln2_b, t2);

    // 7) final MLP: t2 -> hid (GELU) -> out
    tgemm_k<true, false><<<dim3(M_/128, ROWS_KV/128), 256>>>(t2,  mlp_w1, mlp_b1, nullptr, hid, ROWS_KV, M_, E_);
    tgemm_k<false,false><<<dim3(E_/128, ROWS_KV/128), 256>>>(hid, mlp_w2, mlp_b2, nullptr, out, ROWS_KV, E_, M_);
}

// round 5
// speedup vs baseline: 3.6532x; 1.4918x over previous
#include <cuda_runtime.h>
#include <cuda_bf16.h>
#include <math.h>
#include <stdint.h>

// Problem shapes (fixed by the dataset)
#define B_   8
#define HW_  32
#define T_   31
#define NF_  256
#define E_   512
#define M_   2048
#define H_   8
#define DH_  64

#define ROWS_Q   (B_ * NF_)            // 2048
#define ROWS_KV  (B_ * T_ * NF_)       // 63488

// GEMM tiling: CTA 128x128, K-chunk 32, 3-stage cp.async, 4 warps of 64x64
#define TK 32
#define NSTAGE 3
#define STAGE_BYTES 32768              // A 16KB + B 16KB
#define SMEM_TOTAL (NSTAGE * STAGE_BYTES)

// ---------------- static scratch (allocation-free rule) ----------------
__device__ float g_qln [ (size_t)ROWS_Q  * E_ ];
__device__ float g_q   [ (size_t)ROWS_Q  * E_ ];
__device__ float g_kvln[ (size_t)ROWS_KV * E_ ];
__device__ float g_k   [ (size_t)ROWS_KV * E_ ];
__device__ float g_v   [ (size_t)ROWS_KV * E_ ];
__device__ float g_t1  [ (size_t)ROWS_KV * E_ ];
__device__ float g_t2  [ (size_t)ROWS_KV * E_ ];
__device__ float g_hid [ (size_t)ROWS_KV * M_ ];
__device__ float g_wtA [ (size_t)4 * E_ * E_ ];   // wqT wkT wvT woT
__device__ float g_wtB [ (size_t)4 * E_ * M_ ];   // mlpq_w1T mlpq_w2T mlp_w1T mlp_w2T

// ---------------- helpers ----------------
__device__ __forceinline__ float gelu_exact(float x) {
    return 0.5f * x * (1.0f + erff(x * 0.70710678118654752f));
}
__device__ __forceinline__ float tf32r(float x) {
    uint32_t r;
    asm("cvt.rna.tf32.f32 %0, %1;" : "=r"(r) : "f"(x));
    return __uint_as_float(r);
}
__device__ __forceinline__ uint32_t smem_u32(const void* p) {
    uint32_t a;
    asm("{ .reg .u64 t; cvta.to.shared.u64 t, %1; cvt.u32.u64 %0, t; }" : "=r"(a) : "l"(p));
    return a;
}
__device__ __forceinline__ void cp16(uint32_t s, const void* g) {
    asm volatile("cp.async.cg.shared.global [%0], [%1], 16;" :: "r"(s), "l"(g));
}
__device__ __forceinline__ void ldsm4(uint32_t* r, uint32_t a) {
    asm volatile("ldmatrix.sync.aligned.m8n8.x4.shared.b16 {%0,%1,%2,%3}, [%4];"
        : "=r"(r[0]), "=r"(r[1]), "=r"(r[2]), "=r"(r[3]) : "r"(a));
}
__device__ __forceinline__ void mma_tf32(float* d, const uint32_t* a, const uint32_t* b) {
    asm volatile(
        "mma.sync.aligned.m16n8k8.row.col.f32.tf32.tf32.f32 "
        "{%0,%1,%2,%3}, {%4,%5,%6,%7}, {%8,%9}, {%0,%1,%2,%3};"
        : "+f"(d[0]), "+f"(d[1]), "+f"(d[2]), "+f"(d[3])
        : "r"(a[0]), "r"(a[1]), "r"(a[2]), "r"(a[3]), "r"(b[0]), "r"(b[1]));
}

__device__ __forceinline__ float blk_sum(float v, float* sb) {
    #pragma unroll
    for (int o = 16; o; o >>= 1) v += __shfl_xor_sync(0xffffffffu, v, o);
    if ((threadIdx.x & 31) == 0) sb[threadIdx.x >> 5] = v;
    __syncthreads();
    float r = sb[0] + sb[1] + sb[2] + sb[3];
    __syncthreads();
    return r;
}

// ---------------- weight transpose + tf32 rounding: WT[n][k] = rna(W[k][n]) ----------------
__global__ void __launch_bounds__(256) transpose_k(
    const float* __restrict__ W, float* __restrict__ WT, int K, int N)
{
    __shared__ float t[32][33];
    int n0 = blockIdx.x * 32, k0 = blockIdx.y * 32;
    int tx = threadIdx.x & 31, ty = threadIdx.x >> 5;   // 32 x 8
    #pragma unroll
    for (int j = 0; j < 32; j += 8)
        t[ty + j][tx] = W[(size_t)(k0 + ty + j) * N + n0 + tx];
    __syncthreads();
    #pragma unroll
    for (int j = 0; j < 32; j += 8)
        WT[(size_t)(n0 + ty + j) * K + k0 + tx] = tf32r(t[tx][ty + j]);
}

// ---------------- LN of input, split into q-path (t==0) and kv-path (tf32-rounded) ----------------
__global__ void __launch_bounds__(128) ln_in_kernel(
    const float* __restrict__ X,
    const float* __restrict__ gq,  const float* __restrict__ bq,
    const float* __restrict__ gkv, const float* __restrict__ bkv,
    float* __restrict__ out_q, float* __restrict__ out_kv)
{
    __shared__ float sb[4];
    int r = blockIdx.x;
    int b = r >> 13;
    int t = (r >> 8) & 31;
    int n = r & 255;
    int c = threadIdx.x * 4;

    float4 xv = *(const float4*)(X + (size_t)r * E_ + c);
    float s = xv.x + xv.y + xv.z + xv.w;
    float mean = blk_sum(s, sb) * (1.0f / E_);
    float d0 = xv.x - mean, d1 = xv.y - mean, d2 = xv.z - mean, d3 = xv.w - mean;
    float var = blk_sum(d0*d0 + d1*d1 + d2*d2 + d3*d3, sb) * (1.0f / E_);
    float rs = rsqrtf(var + 1e-6f);

    const float *g, *be; float* dst;
    if (t == 0) { g = gq;  be = bq;  dst = out_q  + ((size_t)(b * NF_ + n)) * E_; }
    else        { g = gkv; be = bkv; dst = out_kv + ((size_t)((b * T_ + (t - 1)) * NF_ + n)) * E_; }

    float4 gg = *(const float4*)(g + c);
    float4 bb = *(const float4*)(be + c);
    float4 y;
    y.x = tf32r(d0 * rs * gg.x + bb.x);
    y.y = tf32r(d1 * rs * gg.y + bb.y);
    y.z = tf32r(d2 * rs * gg.z + bb.z);
    y.w = tf32r(d3 * rs * gg.w + bb.w);
    *(float4*)(dst + c) = y;
}

// ---------------- fused double LayerNorm, rounded output ----------------
__global__ void __launch_bounds__(128) dual_ln_kernel(
    const float* __restrict__ X,
    const float* __restrict__ g1, const float* __restrict__ b1,
    const float* __restrict__ g2, const float* __restrict__ b2,
    float* __restrict__ Y)
{
    __shared__ float sb[4];
    size_t r = blockIdx.x;
    int c = threadIdx.x * 4;
    float4 xv = *(const float4*)(X + r * E_ + c);

    float s = xv.x + xv.y + xv.z + xv.w;
    float mean = blk_sum(s, sb) * (1.0f / E_);
    float d0 = xv.x - mean, d1 = xv.y - mean, d2 = xv.z - mean, d3 = xv.w - mean;
    float var = blk_sum(d0*d0 + d1*d1 + d2*d2 + d3*d3, sb) * (1.0f / E_);
    float rs = rsqrtf(var + 1e-6f);

    float4 gg = *(const float4*)(g1 + c);
    float4 bb = *(const float4*)(b1 + c);
    float y0 = d0 * rs * gg.x + bb.x;
    float y1 = d1 * rs * gg.y + bb.y;
    float y2 = d2 * rs * gg.z + bb.z;
    float y3 = d3 * rs * gg.w + bb.w;

    float s2 = y0 + y1 + y2 + y3;
    float mean2 = blk_sum(s2, sb) * (1.0f / E_);
    float e0 = y0 - mean2, e1 = y1 - mean2, e2 = y2 - mean2, e3 = y3 - mean2;
    float var2 = blk_sum(e0*e0 + e1*e1 + e2*e2 + e3*e3, sb) * (1.0f / E_);
    float rs2 = rsqrtf(var2 + 1e-6f);

    float4 gg2 = *(const float4*)(g2 + c);
    float4 bb2 = *(const float4*)(b2 + c);
    float4 out;
    out.x = tf32r(e0 * rs2 * gg2.x + bb2.x);
    out.y = tf32r(e1 * rs2 * gg2.y + bb2.y);
    out.z = tf32r(e2 * rs2 * gg2.z + bb2.z);
    out.w = tf32r(e3 * rs2 * gg2.w + bb2.w);
    *(float4*)(Y + r * E_ + c) = out;
}

// ---------------- tf32 mma.sync GEMM v2: C = epi(A @ BT^T + bias [+res]) ----------------
// A: Mrows x K row-major (tf32 patterns). BT: N x K row-major (tf32 patterns).
// CTA 128x128, TK=32, 3-stage cp.async, 4 warps (2x2) of 64x64.
// SW128 swizzle: row stride 128B, granule (16B) index ^= row&7. ldmatrix fragment loads.
template<bool DO_GELU, bool DO_RES, bool DO_ROUND>
__global__ void __launch_bounds__(128, 2) tgemm2(
    const float* __restrict__ A, const float* __restrict__ BT,
    const float* __restrict__ bias, const float* __restrict__ res,
    float* __restrict__ C, int Mrows, int N, int K)
{
    extern __shared__ char dsm[];
    const uint32_t sb0 = smem_u32(dsm);
    const int tid = threadIdx.x, warp = tid >> 5, lane = tid & 31;
    const int brow = blockIdx.y * 128;
    const int bcol = blockIdx.x * 128;
    const int wm = (warp >> 1) * 64, wn = (warp & 1) * 64;

    // fill mapping: thread -> (row = tid/8 + 16*i, granule = tid%8), coalesced 128B rows
    const int rf = tid >> 3, gf = tid & 7;
    const uint32_t fso = (uint32_t)rf * 128 + ((gf ^ (rf & 7)) << 4);  // + i*2048
    const float* gA = A  + (size_t)(brow + rf) * K + gf * 4;
    const float* gB = BT + (size_t)(bcol + rf) * K + gf * 4;

    // ldmatrix lane geometry
    const int r7 = lane & 7, tile = lane >> 3;
    const int arow = (tile & 1) * 8 + r7;      // row within 16-row A tile
    const int ah   = tile >> 1;                // k-granule half
    const int bnr  = (tile >> 1) * 8 + r7;     // n-row within 16-n B tile
    const int bh   = tile & 1;

    float acc[4][8][4];
    #pragma unroll
    for (int mi = 0; mi < 4; mi++)
        #pragma unroll
        for (int ni = 0; ni < 8; ni++)
            #pragma unroll
            for (int r = 0; r < 4; r++) acc[mi][ni][r] = 0.0f;

    const int nkt = K / TK;

    auto fill = [&](int kt) {
        const int st = kt % NSTAGE;
        uint32_t dA = sb0 + st * STAGE_BYTES;
        uint32_t dB = dA + 16384;
        const float* ga = gA + kt * TK;
        const float* gb = gB + kt * TK;
        #pragma unroll
        for (int i = 0; i < 8; i++) {
            uint32_t so = fso + (uint32_t)i * 2048;     // 16 rows * 128B
            cp16(dA + so, ga + (size_t)i * 16 * K);
            cp16(dB + so, gb + (size_t)i * 16 * K);
        }
        asm volatile("cp.async.commit_group;" ::: "memory");
    };

    fill(0);
    if (nkt > 1) fill(1);

    for (int kt = 0; kt < nkt; kt++) {
        if (kt + 1 < nkt) asm volatile("cp.async.wait_group 1;" ::: "memory");
        else              asm volatile("cp.async.wait_group 0;" ::: "memory");
        __syncthreads();
        if (kt + 2 < nkt) fill(kt + 2);

        const int st = kt % NSTAGE;
        const uint32_t sA = sb0 + st * STAGE_BYTES;
        const uint32_t sB = sA + 16384;

        #pragma unroll
        for (int ks = 0; ks < 4; ks++) {
            uint32_t af[4][4], bq[4][4];
            #pragma unroll
            for (int mi = 0; mi < 4; mi++) {
                int row = wm + mi * 16 + arow;
                uint32_t ad = sA + (uint32_t)row * 128 + ((((ks << 1) | ah) ^ r7) << 4);
                ldsm4(af[mi], ad);
            }
            #pragma unroll
            for (int n2 = 0; n2 < 4; n2++) {
                int nr = wn + n2 * 16 + bnr;
                uint32_t bd = sB + (uint32_t)nr * 128 + ((((ks << 1) | bh) ^ r7) << 4);
                ldsm4(bq[n2], bd);
            }
            #pragma unroll
            for (int mi = 0; mi < 4; mi++)
                #pragma unroll
                for (int ni = 0; ni < 8; ni++)
                    mma_tf32(acc[mi][ni], af[mi], &bq[ni >> 1][(ni & 1) * 2]);
        }
    }

    // ---- epilogue ----
    const int g = lane >> 2, q = lane & 3;
    #pragma unroll
    for (int ni = 0; ni < 8; ni++) {
        int col = bcol + wn + ni * 8 + q * 2;
        float bb0 = bias[col], bb1 = bias[col + 1];
        #pragma unroll
        for (int mi = 0; mi < 4; mi++) {
            #pragma unroll
            for (int h = 0; h < 2; h++) {
                int row = brow + wm + mi * 16 + g + h * 8;
                size_t off = (size_t)row * N + col;
                float v0 = acc[mi][ni][h * 2 + 0] + bb0;
                float v1 = acc[mi][ni][h * 2 + 1] + bb1;
                if (DO_RES) {
                    float2 rr = *(const float2*)(res + off);
                    v0 += rr.x; v1 += rr.y;
                }
                if (DO_GELU) { v0 = gelu_exact(v0); v1 = gelu_exact(v1); }
                if (DO_ROUND) { v0 = tf32r(v0); v1 = tf32r(v1); }
                float2 o; o.x = v0; o.y = v1;
                *(float2*)(C + off) = o;
            }
        }
    }
}

// ---------------- fused attention (fp32, rounded output) ----------------
__global__ void __launch_bounds__(256, 1) attn_kernel(
    const float* __restrict__ Q, const float* __restrict__ Kg,
    const float* __restrict__ Vg, float* __restrict__ O)
{
    __shared__ float kbuf[16][64];
    __shared__ float vbuf[16][64];

    int idx = blockIdx.x;
    int h = idx % H_;
    int bt = idx / H_;
    int b = bt / T_;

    int n = threadIdx.x;
    const float* qrow = Q + ((size_t)(b * NF_ + n)) * E_ + h * DH_;
    float q[64];
    #pragma unroll
    for (int i = 0; i < 16; i++) *(float4*)&q[i * 4] = *(const float4*)&qrow[i * 4];

    float o[64];
    #pragma unroll
    for (int i = 0; i < 64; i++) o[i] = 0.0f;
    float mmax = -3.4e38f, l = 0.0f;

    size_t base = (size_t)bt * NF_ * E_ + h * DH_;
    const int jr = threadIdx.x >> 4;
    const int dc = (threadIdx.x & 15) * 4;

    for (int j0 = 0; j0 < NF_; j0 += 16) {
        __syncthreads();
        *(float4*)&kbuf[jr][dc] = *(const float4*)(Kg + base + (size_t)(j0 + jr) * E_ + dc);
        *(float4*)&vbuf[jr][dc] = *(const float4*)(Vg + base + (size_t)(j0 + jr) * E_ + dc);
        __syncthreads();

        #pragma unroll
        for (int jj = 0; jj < 16; jj++) {
            float s = 0.0f;
            #pragma unroll
            for (int d = 0; d < 64; d++) s = fmaf(q[d], kbuf[jj][d], s);
            s *= 0.125f;
            float mnew = fmaxf(mmax, s);
            float alpha = __expf(mmax - mnew);
            float p = __expf(s - mnew);
            l = l * alpha + p;
            #pragma unroll
            for (int d = 0; d < 64; d++) o[d] = o[d] * alpha + p * vbuf[jj][d];
            mmax = mnew;
        }
    }

    float inv = 1.0f / l;
    float* orow = O + ((size_t)bt * NF_ + n) * E_ + h * DH_;
    #pragma unroll
    for (int i = 0; i < 16; i++) {
        float4 out;
        out.x = tf32r(o[i * 4 + 0] * inv);
        out.y = tf32r(o[i * 4 + 1] * inv);
        out.z = tf32r(o[i * 4 + 2] * inv);
        out.w = tf32r(o[i * 4 + 3] * inv);
        *(float4*)&orow[i * 4] = out;
    }
}

// ---------------- host ----------------
extern "C" void kernel_launch(void* const* d_in, const int* in_sizes, int n_in,
                              void* d_out, int out_size)
{
    const float* inputs  = (const float*)d_in[0];
    const float* wq      = (const float*)d_in[1];
    const float* wk      = (const float*)d_in[2];
    const float* wv      = (const float*)d_in[3];
    const float* bq      = (const float*)d_in[4];
    const float* bk      = (const float*)d_in[5];
    const float* bv      = (const float*)d_in[6];
    const float* wo      = (const float*)d_in[7];
    const float* bo      = (const float*)d_in[8];
    const float* lnq_g   = (const float*)d_in[9];
    const float* lnq_b   = (const float*)d_in[10];
    const float* lnkv_g  = (const float*)d_in[11];
    const float* lnkv_b  = (const float*)d_in[12];
    const float* mlpq_w1 = (const float*)d_in[13];
    const float* mlpq_b1 = (const float*)d_in[14];
    const float* mlpq_w2 = (const float*)d_in[15];
    const float* mlpq_b2 = (const float*)d_in[16];
    const float* resln_g = (const float*)d_in[17];
    const float* resln_b = (const float*)d_in[18];
    const float* ln2_g   = (const float*)d_in[19];
    const float* ln2_b   = (const float*)d_in[20];
    const float* mlp_w1  = (const float*)d_in[21];
    const float* mlp_b1  = (const float*)d_in[22];
    const float* mlp_w2  = (const float*)d_in[23];
    const float* mlp_b2  = (const float*)d_in[24];
    float* out = (float*)d_out;

    float *qln, *q, *kvln, *k, *v, *t1, *t2, *hid, *wtA, *wtB;
    cudaGetSymbolAddress((void**)&qln,  g_qln);
    cudaGetSymbolAddress((void**)&q,    g_q);
    cudaGetSymbolAddress((void**)&kvln, g_kvln);
    cudaGetSymbolAddress((void**)&k,    g_k);
    cudaGetSymbolAddress((void**)&v,    g_v);
    cudaGetSymbolAddress((void**)&t1,   g_t1);
    cudaGetSymbolAddress((void**)&t2,   g_t2);
    cudaGetSymbolAddress((void**)&hid,  g_hid);
    cudaGetSymbolAddress((void**)&wtA,  g_wtA);
    cudaGetSymbolAddress((void**)&wtB,  g_wtB);

    float* wqT = wtA;
    float* wkT = wtA + (size_t)E_ * E_;
    float* wvT = wtA + (size_t)2 * E_ * E_;
    float* woT = wtA + (size_t)3 * E_ * E_;
    float* mq1T = wtB;                            // (M, E)
    float* mq2T = wtB + (size_t)E_ * M_;          // (E, M)
    float* m1T  = wtB + (size_t)2 * E_ * M_;      // (M, E)
    float* m2T  = wtB + (size_t)3 * E_ * M_;      // (E, M)

    cudaFuncSetAttribute(tgemm2<false,false,false>, cudaFuncAttributeMaxDynamicSharedMemorySize, SMEM_TOTAL);
    cudaFuncSetAttribute(tgemm2<false,false,true >, cudaFuncAttributeMaxDynamicSharedMemorySize, SMEM_TOTAL);
    cudaFuncSetAttribute(tgemm2<true ,false,true >, cudaFuncAttributeMaxDynamicSharedMemorySize, SMEM_TOTAL);
    cudaFuncSetAttribute(tgemm2<false,true ,false>, cudaFuncAttributeMaxDynamicSharedMemorySize, SMEM_TOTAL);

    // 0) weight transposes (+ tf32 rounding)
    transpose_k<<<dim3(E_/32, E_/32), 256>>>(wq, wqT, E_, E_);
    transpose_k<<<dim3(E_/32, E_/32), 256>>>(wk, wkT, E_, E_);
    transpose_k<<<dim3(E_/32, E_/32), 256>>>(wv, wvT, E_, E_);
    transpose_k<<<dim3(E_/32, E_/32), 256>>>(wo, woT, E_, E_);
    transpose_k<<<dim3(M_/32, E_/32), 256>>>(mlpq_w1, mq1T, E_, M_);
    transpose_k<<<dim3(E_/32, M_/32), 256>>>(mlpq_w2, mq2T, M_, E_);
    transpose_k<<<dim3(M_/32, E_/32), 256>>>(mlp_w1,  m1T,  E_, M_);
    transpose_k<<<dim3(E_/32, M_/32), 256>>>(mlp_w2,  m2T,  M_, E_);

    // 1) LayerNorms of the input (tf32-rounded outputs)
    ln_in_kernel<<<B_ * HW_ * NF_, 128>>>(inputs, lnq_g, lnq_b, lnkv_g, lnkv_b, qln, kvln);

    // 2) projections
    tgemm2<false,false,false><<<dim3(E_/128, ROWS_Q/128),  128, SMEM_TOTAL>>>(qln,  wqT, bq, nullptr, q, ROWS_Q,  E_, E_);
    tgemm2<false,false,false><<<dim3(E_/128, ROWS_KV/128), 128, SMEM_TOTAL>>>(kvln, wkT, bk, nullptr, k, ROWS_KV, E_, E_);
    tgemm2<false,false,false><<<dim3(E_/128, ROWS_KV/128), 128, SMEM_TOTAL>>>(kvln, wvT, bv, nullptr, v, ROWS_KV, E_, E_);

    // 3) attention -> t1 (rounded)
    attn_kernel<<<B_ * T_ * H_, 256>>>(q, k, v, t1);

    // 4) out projection -> t2 (rounded, feeds mlpq)
    tgemm2<false,false,true ><<<dim3(E_/128, ROWS_KV/128), 128, SMEM_TOTAL>>>(t1, woT, bo, nullptr, t2, ROWS_KV, E_, E_);

    // 5) mlp_q: t2 -> hid (GELU, rounded) -> t1 (+ residual kvln)
    tgemm2<true ,false,true ><<<dim3(M_/128, ROWS_KV/128), 128, SMEM_TOTAL>>>(t2, mq1T, mlpq_b1, nullptr, hid, ROWS_KV, M_, E_);
    tgemm2<false,true ,false><<<dim3(E_/128, ROWS_KV/128), 128, SMEM_TOTAL>>>(hid, mq2T, mlpq_b2, kvln,  t1,  ROWS_KV, E_, M_);

    // 6) res_ln then ln_2 fused: t1 -> t2 (rounded)
    dual_ln_kernel<<<ROWS_KV, 128>>>(t1, resln_g, resln_b, ln2_g, ln2_b, t2);

    // 7) final MLP: t2 -> hid (GELU, rounded) -> out
    tgemm2<true ,false,true ><<<dim3(M_/128, ROWS_KV/128), 128, SMEM_TOTAL>>>(t2,  m1T, mlp_b1, nullptr, hid, ROWS_KV, M_, E_);
    tgemm2<false,false,false><<<dim3(E_/128, ROWS_KV/128), 128, SMEM_TOTAL>>>(hid, m2T, mlp_b2, nullptr, out, ROWS_KV, E_, M_);
}

// round 6
// speedup vs baseline: 4.7783x; 1.3080x over previous
#include <cuda_runtime.h>
#include <cuda_bf16.h>
#include <math.h>
#include <stdint.h>

// Problem shapes (fixed by the dataset)
#define B_   8
#define HW_  32
#define T_   31
#define NF_  256
#define E_   512
#define M_   2048
#define H_   8
#define DH_  64

#define ROWS_Q   (B_ * NF_)            // 2048
#define ROWS_KV  (B_ * T_ * NF_)       // 63488

// GEMM tiling: CTA 128x128, K-chunk 32, 3-stage cp.async, 4 warps of 64x64
#define TK 32
#define NSTAGE 3
#define STAGE_BYTES 32768              // A 16KB + B 16KB
#define SMEM_TOTAL (NSTAGE * STAGE_BYTES)

// Attention smem layout (floats, row stride 72)
#define AQ_OFF 0
#define AP_OFF (256*72)
#define AK_OFF (512*72)
#define AV_OFF (512*72 + 2*64*72)
#define ATTN_SMEM ((512*72 + 4*64*72) * 4)   // 221184 bytes

// ---------------- static scratch (allocation-free rule) ----------------
__device__ float g_qln [ (size_t)ROWS_Q  * E_ ];
__device__ float g_q   [ (size_t)ROWS_Q  * E_ ];
__device__ float g_kvln[ (size_t)ROWS_KV * E_ ];
__device__ float g_kv  [ (size_t)ROWS_KV * 1024 ];
__device__ float g_t1  [ (size_t)ROWS_KV * E_ ];
__device__ float g_t2  [ (size_t)ROWS_KV * E_ ];
__device__ float g_hid [ (size_t)ROWS_KV * M_ ];
__device__ float g_wtA [ (size_t)4 * E_ * E_ ];   // wkvT(1024x512) + woT + (512x512 spare from layout)
__device__ float g_wtB [ (size_t)4 * E_ * M_ ];   // mlpq_w1T mlpq_w2T mlp_w1T mlp_w2T
__device__ float g_wqT [ (size_t)E_ * E_ ];
__device__ float g_bkv [ 1024 ];

// ---------------- helpers ----------------
__device__ __forceinline__ float gelu_exact(float x) {
    return 0.5f * x * (1.0f + erff(x * 0.70710678118654752f));
}
__device__ __forceinline__ float tf32r(float x) {
    uint32_t r;
    asm("cvt.rna.tf32.f32 %0, %1;" : "=r"(r) : "f"(x));
    return __uint_as_float(r);
}
__device__ __forceinline__ uint32_t smem_u32(const void* p) {
    uint32_t a;
    asm("{ .reg .u64 t; cvta.to.shared.u64 t, %1; cvt.u32.u64 %0, t; }" : "=r"(a) : "l"(p));
    return a;
}
__device__ __forceinline__ void cp16(uint32_t s, const void* g) {
    asm volatile("cp.async.cg.shared.global [%0], [%1], 16;" :: "r"(s), "l"(g));
}
__device__ __forceinline__ void ldsm4(uint32_t* r, uint32_t a) {
    asm volatile("ldmatrix.sync.aligned.m8n8.x4.shared.b16 {%0,%1,%2,%3}, [%4];"
        : "=r"(r[0]), "=r"(r[1]), "=r"(r[2]), "=r"(r[3]) : "r"(a));
}
__device__ __forceinline__ void mma_tf32(float* d, const uint32_t* a, const uint32_t* b) {
    asm volatile(
        "mma.sync.aligned.m16n8k8.row.col.f32.tf32.tf32.f32 "
        "{%0,%1,%2,%3}, {%4,%5,%6,%7}, {%8,%9}, {%0,%1,%2,%3};"
        : "+f"(d[0]), "+f"(d[1]), "+f"(d[2]), "+f"(d[3])
        : "r"(a[0]), "r"(a[1]), "r"(a[2]), "r"(a[3]), "r"(b[0]), "r"(b[1]));
}

__device__ __forceinline__ float blk_sum(float v, float* sb) {
    #pragma unroll
    for (int o = 16; o; o >>= 1) v += __shfl_xor_sync(0xffffffffu, v, o);
    if ((threadIdx.x & 31) == 0) sb[threadIdx.x >> 5] = v;
    __syncthreads();
    float r = sb[0] + sb[1] + sb[2] + sb[3];
    __syncthreads();
    return r;
}

// ---------------- weight transpose + tf32 rounding: WT[n][k] = rna(W[k][n]) ----------------
__global__ void __launch_bounds__(256) transpose_k(
    const float* __restrict__ W, float* __restrict__ WT, int K, int N)
{
    __shared__ float t[32][33];
    int n0 = blockIdx.x * 32, k0 = blockIdx.y * 32;
    int tx = threadIdx.x & 31, ty = threadIdx.x >> 5;   // 32 x 8
    #pragma unroll
    for (int j = 0; j < 32; j += 8)
        t[ty + j][tx] = W[(size_t)(k0 + ty + j) * N + n0 + tx];
    __syncthreads();
    #pragma unroll
    for (int j = 0; j < 32; j += 8)
        WT[(size_t)(n0 + ty + j) * K + k0 + tx] = tf32r(t[tx][ty + j]);
}

__global__ void concat_bias_k(const float* __restrict__ bk, const float* __restrict__ bv,
                              float* __restrict__ dst)
{
    int i = blockIdx.x * 256 + threadIdx.x;
    if (i < 512)       dst[i] = bk[i];
    else if (i < 1024) dst[i] = bv[i - 512];
}

// ---------------- LN of input, split into q-path (t==0) and kv-path (tf32-rounded) ----------------
__global__ void __launch_bounds__(128) ln_in_kernel(
    const float* __restrict__ X,
    const float* __restrict__ gq,  const float* __restrict__ bq,
    const float* __restrict__ gkv, const float* __restrict__ bkv,
    float* __restrict__ out_q, float* __restrict__ out_kv)
{
    __shared__ float sb[4];
    int r = blockIdx.x;
    int b = r >> 13;
    int t = (r >> 8) & 31;
    int n = r & 255;
    int c = threadIdx.x * 4;

    float4 xv = *(const float4*)(X + (size_t)r * E_ + c);
    float s = xv.x + xv.y + xv.z + xv.w;
    float mean = blk_sum(s, sb) * (1.0f / E_);
    float d0 = xv.x - mean, d1 = xv.y - mean, d2 = xv.z - mean, d3 = xv.w - mean;
    float var = blk_sum(d0*d0 + d1*d1 + d2*d2 + d3*d3, sb) * (1.0f / E_);
    float rs = rsqrtf(var + 1e-6f);

    const float *g, *be; float* dst;
    if (t == 0) { g = gq;  be = bq;  dst = out_q  + ((size_t)(b * NF_ + n)) * E_; }
    else        { g = gkv; be = bkv; dst = out_kv + ((size_t)((b * T_ + (t - 1)) * NF_ + n)) * E_; }

    float4 gg = *(const float4*)(g + c);
    float4 bb = *(const float4*)(be + c);
    float4 y;
    y.x = tf32r(d0 * rs * gg.x + bb.x);
    y.y = tf32r(d1 * rs * gg.y + bb.y);
    y.z = tf32r(d2 * rs * gg.z + bb.z);
    y.w = tf32r(d3 * rs * gg.w + bb.w);
    *(float4*)(dst + c) = y;
}

// ---------------- fused double LayerNorm, rounded output ----------------
__global__ void __launch_bounds__(128) dual_ln_kernel(
    const float* __restrict__ X,
    const float* __restrict__ g1, const float* __restrict__ b1,
    const float* __restrict__ g2, const float* __restrict__ b2,
    float* __restrict__ Y)
{
    __shared__ float sb[4];
    size_t r = blockIdx.x;
    int c = threadIdx.x * 4;
    float4 xv = *(const float4*)(X + r * E_ + c);

    float s = xv.x + xv.y + xv.z + xv.w;
    float mean = blk_sum(s, sb) * (1.0f / E_);
    float d0 = xv.x - mean, d1 = xv.y - mean, d2 = xv.z - mean, d3 = xv.w - mean;
    float var = blk_sum(d0*d0 + d1*d1 + d2*d2 + d3*d3, sb) * (1.0f / E_);
    float rs = rsqrtf(var + 1e-6f);

    float4 gg = *(const float4*)(g1 + c);
    float4 bb = *(const float4*)(b1 + c);
    float y0 = d0 * rs * gg.x + bb.x;
    float y1 = d1 * rs * gg.y + bb.y;
    float y2 = d2 * rs * gg.z + bb.z;
    float y3 = d3 * rs * gg.w + bb.w;

    float s2 = y0 + y1 + y2 + y3;
    float mean2 = blk_sum(s2, sb) * (1.0f / E_);
    float e0 = y0 - mean2, e1 = y1 - mean2, e2 = y2 - mean2, e3 = y3 - mean2;
    float var2 = blk_sum(e0*e0 + e1*e1 + e2*e2 + e3*e3, sb) * (1.0f / E_);
    float rs2 = rsqrtf(var2 + 1e-6f);

    float4 gg2 = *(const float4*)(g2 + c);
    float4 bb2 = *(const float4*)(b2 + c);
    float4 out;
    out.x = tf32r(e0 * rs2 * gg2.x + bb2.x);
    out.y = tf32r(e1 * rs2 * gg2.y + bb2.y);
    out.z = tf32r(e2 * rs2 * gg2.z + bb2.z);
    out.w = tf32r(e3 * rs2 * gg2.w + bb2.w);
    *(float4*)(Y + r * E_ + c) = out;
}

// ---------------- tf32 mma.sync GEMM: C = epi(A @ BT^T + bias [+res]) ----------------
template<bool DO_GELU, bool DO_RES, bool DO_ROUND>
__global__ void __launch_bounds__(128, 2) tgemm2(
    const float* __restrict__ A, const float* __restrict__ BT,
    const float* __restrict__ bias, const float* __restrict__ res,
    float* __restrict__ C, int Mrows, int N, int K)
{
    extern __shared__ char dsm[];
    const uint32_t sb0 = smem_u32(dsm);
    const int tid = threadIdx.x, warp = tid >> 5, lane = tid & 31;
    const int brow = blockIdx.y * 128;
    const int bcol = blockIdx.x * 128;
    const int wm = (warp >> 1) * 64, wn = (warp & 1) * 64;

    const int rf = tid >> 3, gf = tid & 7;
    const uint32_t fso = (uint32_t)rf * 128 + ((gf ^ (rf & 7)) << 4);
    const float* gA = A  + (size_t)(brow + rf) * K + gf * 4;
    const float* gB = BT + (size_t)(bcol + rf) * K + gf * 4;

    const int r7 = lane & 7, tile = lane >> 3;
    const int arow = (tile & 1) * 8 + r7;
    const int ah   = tile >> 1;
    const int bnr  = (tile >> 1) * 8 + r7;
    const int bh   = tile & 1;

    float acc[4][8][4];
    #pragma unroll
    for (int mi = 0; mi < 4; mi++)
        #pragma unroll
        for (int ni = 0; ni < 8; ni++)
            #pragma unroll
            for (int r = 0; r < 4; r++) acc[mi][ni][r] = 0.0f;

    const int nkt = K / TK;

    auto fill = [&](int kt) {
        const int st = kt % NSTAGE;
        uint32_t dA = sb0 + st * STAGE_BYTES;
        uint32_t dB = dA + 16384;
        const float* ga = gA + kt * TK;
        const float* gb = gB + kt * TK;
        #pragma unroll
        for (int i = 0; i < 8; i++) {
            uint32_t so = fso + (uint32_t)i * 2048;
            cp16(dA + so, ga + (size_t)i * 16 * K);
            cp16(dB + so, gb + (size_t)i * 16 * K);
        }
        asm volatile("cp.async.commit_group;" ::: "memory");
    };

    fill(0);
    if (nkt > 1) fill(1);

    for (int kt = 0; kt < nkt; kt++) {
        if (kt + 1 < nkt) asm volatile("cp.async.wait_group 1;" ::: "memory");
        else              asm volatile("cp.async.wait_group 0;" ::: "memory");
        __syncthreads();
        if (kt + 2 < nkt) fill(kt + 2);

        const int st = kt % NSTAGE;
        const uint32_t sA = sb0 + st * STAGE_BYTES;
        const uint32_t sB = sA + 16384;

        #pragma unroll
        for (int ks = 0; ks < 4; ks++) {
            uint32_t af[4][4], bq[4][4];
            #pragma unroll
            for (int mi = 0; mi < 4; mi++) {
                int row = wm + mi * 16 + arow;
                uint32_t ad = sA + (uint32_t)row * 128 + ((((ks << 1) | ah) ^ r7) << 4);
                ldsm4(af[mi], ad);
            }
            #pragma unroll
            for (int n2 = 0; n2 < 4; n2++) {
                int nr = wn + n2 * 16 + bnr;
                uint32_t bd = sB + (uint32_t)nr * 128 + ((((ks << 1) | bh) ^ r7) << 4);
                ldsm4(bq[n2], bd);
            }
            #pragma unroll
            for (int mi = 0; mi < 4; mi++)
                #pragma unroll
                for (int ni = 0; ni < 8; ni++)
                    mma_tf32(acc[mi][ni], af[mi], &bq[ni >> 1][(ni & 1) * 2]);
        }
    }

    const int g = lane >> 2, q = lane & 3;
    #pragma unroll
    for (int ni = 0; ni < 8; ni++) {
        int col = bcol + wn + ni * 8 + q * 2;
        float bb0 = bias[col], bb1 = bias[col + 1];
        #pragma unroll
        for (int mi = 0; mi < 4; mi++) {
            #pragma unroll
            for (int h = 0; h < 2; h++) {
                int row = brow + wm + mi * 16 + g + h * 8;
                size_t off = (size_t)row * N + col;
                float v0 = acc[mi][ni][h * 2 + 0] + bb0;
                float v1 = acc[mi][ni][h * 2 + 1] + bb1;
                if (DO_RES) {
                    float2 rr = *(const float2*)(res + off);
                    v0 += rr.x; v1 += rr.y;
                }
                if (DO_GELU) { v0 = gelu_exact(v0); v1 = gelu_exact(v1); }
                if (DO_ROUND) { v0 = tf32r(v0); v1 = tf32r(v1); }
                float2 o; o.x = v0; o.y = v1;
                *(float2*)(C + off) = o;
            }
        }
    }
}

// ---------------- tensorized flash attention (tf32 mma) ----------------
// CTA per (b,t,h): 8 warps x 32 queries. Q (pre-scaled) resident; K/V in 64-key
// double-buffered cp.async chunks from g_kv (stride 1024: k at +0, v at +512).
__global__ void __launch_bounds__(256, 1) attn_mma(
    const float* __restrict__ Q, const float* __restrict__ KV, float* __restrict__ O)
{
    extern __shared__ float sm[];
    float* Qs = sm + AQ_OFF;            // [256][72]
    float* Ps = sm + AP_OFF;            // [256][72]
    float* Ks = sm + AK_OFF;            // [2][64][72]
    float* Vs = sm + AV_OFF;            // [2][64][72]

    const int idx = blockIdx.x;
    const int h = idx & 7;
    const int bt = idx >> 3;
    const int b = bt / T_;
    const int tid = threadIdx.x, warp = tid >> 5, lane = tid & 31;
    const int g = lane >> 2, q = lane & 3;
    const int wm = warp * 32;

    // load Q rows (scaled by 1/8)
    {
        const float* gq = Q + (size_t)(b * NF_) * E_ + h * DH_;
        #pragma unroll
        for (int i = tid; i < 256 * 16; i += 256) {
            int r = i >> 4, c4 = (i & 15) * 4;
            float4 v = *(const float4*)(gq + (size_t)r * E_ + c4);
            float* d = Qs + r * 72 + c4;
            d[0] = v.x * 0.125f; d[1] = v.y * 0.125f;
            d[2] = v.z * 0.125f; d[3] = v.w * 0.125f;
        }
    }

    const float* kvbase = KV + (size_t)bt * NF_ * 1024 + h * DH_;
    auto fillkv = [&](int ch) {
        int st = ch & 1;
        #pragma unroll
        for (int i = tid; i < 64 * 16; i += 256) {
            int r = i >> 4, c4 = (i & 15) * 4;
            const float* src = kvbase + (size_t)(ch * 64 + r) * 1024 + c4;
            cp16(smem_u32(Ks + (st * 64 + r) * 72 + c4), src);
            cp16(smem_u32(Vs + (st * 64 + r) * 72 + c4), src + 512);
        }
        asm volatile("cp.async.commit_group;" ::: "memory");
    };

    fillkv(0);

    float o[2][8][4];
    #pragma unroll
    for (int mi = 0; mi < 2; mi++)
        #pragma unroll
        for (int nd = 0; nd < 8; nd++)
            #pragma unroll
            for (int r = 0; r < 4; r++) o[mi][nd][r] = 0.0f;
    float mrow[2][2] = {{-1e30f, -1e30f}, {-1e30f, -1e30f}};
    float lrow[2][2] = {{0.0f, 0.0f}, {0.0f, 0.0f}};

    for (int ch = 0; ch < 4; ch++) {
        asm volatile("cp.async.wait_group 0;" ::: "memory");
        __syncthreads();                       // chunk data visible; prev buffer free
        if (ch + 1 < 4) fillkv(ch + 1);

        const float* Kst = Ks + (ch & 1) * 64 * 72;
        const float* Vst = Vs + (ch & 1) * 64 * 72;

        // ---- S = (Q/8) K^T ----
        float s[2][8][4];
        #pragma unroll
        for (int mi = 0; mi < 2; mi++)
            #pragma unroll
            for (int ni = 0; ni < 8; ni++)
                #pragma unroll
                for (int r = 0; r < 4; r++) s[mi][ni][r] = 0.0f;

        #pragma unroll
        for (int ks = 0; ks < 8; ks++) {
            uint32_t af[2][4], bf[8][2];
            #pragma unroll
            for (int mi = 0; mi < 2; mi++) {
                const float* qp = Qs + (wm + mi * 16 + g) * 72 + ks * 8 + q;
                af[mi][0] = __float_as_uint(qp[0]);
                af[mi][1] = __float_as_uint(qp[8 * 72]);
                af[mi][2] = __float_as_uint(qp[4]);
                af[mi][3] = __float_as_uint(qp[8 * 72 + 4]);
            }
            #pragma unroll
            for (int ni = 0; ni < 8; ni++) {
                const float* kp = Kst + (ni * 8 + g) * 72 + ks * 8 + q;
                bf[ni][0] = __float_as_uint(kp[0]);
                bf[ni][1] = __float_as_uint(kp[4]);
            }
            #pragma unroll
            for (int mi = 0; mi < 2; mi++)
                #pragma unroll
                for (int ni = 0; ni < 8; ni++)
                    mma_tf32(s[mi][ni], af[mi], bf[ni]);
        }

        // ---- online softmax on fragments ----
        #pragma unroll
        for (int mi = 0; mi < 2; mi++) {
            #pragma unroll
            for (int hh = 0; hh < 2; hh++) {
                float rm = -1e30f;
                #pragma unroll
                for (int ni = 0; ni < 8; ni++)
                    rm = fmaxf(rm, fmaxf(s[mi][ni][hh * 2], s[mi][ni][hh * 2 + 1]));
                rm = fmaxf(rm, __shfl_xor_sync(0xffffffffu, rm, 1));
                rm = fmaxf(rm, __shfl_xor_sync(0xffffffffu, rm, 2));
                float mnew = fmaxf(mrow[mi][hh], rm);
                float alpha = __expf(mrow[mi][hh] - mnew);
                mrow[mi][hh] = mnew;
                float rs = 0.0f;
                #pragma unroll
                for (int ni = 0; ni < 8; ni++) {
                    float p0 = __expf(s[mi][ni][hh * 2]     - mnew);
                    float p1 = __expf(s[mi][ni][hh * 2 + 1] - mnew);
                    rs += p0 + p1;
                    s[mi][ni][hh * 2]     = p0;
                    s[mi][ni][hh * 2 + 1] = p1;
                }
                rs += __shfl_xor_sync(0xffffffffu, rs, 1);
                rs += __shfl_xor_sync(0xffffffffu, rs, 2);
                lrow[mi][hh] = lrow[mi][hh] * alpha + rs;
                #pragma unroll
                for (int nd = 0; nd < 8; nd++) {
                    o[mi][nd][hh * 2]     *= alpha;
                    o[mi][nd][hh * 2 + 1] *= alpha;
                }
            }
        }

        // ---- P through smem (layout exchange), then O += P V ----
        __syncwarp();
        #pragma unroll
        for (int mi = 0; mi < 2; mi++) {
            #pragma unroll
            for (int ni = 0; ni < 8; ni++) {
                float* pp = Ps + (wm + mi * 16 + g) * 72 + ni * 8 + 2 * q;
                pp[0]          = tf32r(s[mi][ni][0]);
                pp[1]          = tf32r(s[mi][ni][1]);
                pp[8 * 72]     = tf32r(s[mi][ni][2]);
                pp[8 * 72 + 1] = tf32r(s[mi][ni][3]);
            }
        }
        __syncwarp();

        #pragma unroll
        for (int ks = 0; ks < 8; ks++) {
            uint32_t af[2][4], bf[8][2];
            #pragma unroll
            for (int mi = 0; mi < 2; mi++) {
                const float* pp = Ps + (wm + mi * 16 + g) * 72 + ks * 8 + q;
                af[mi][0] = __float_as_uint(pp[0]);
                af[mi][1] = __float_as_uint(pp[8 * 72]);
                af[mi][2] = __float_as_uint(pp[4]);
                af[mi][3] = __float_as_uint(pp[8 * 72 + 4]);
            }
            #pragma unroll
            for (int nd = 0; nd < 8; nd++) {
                const float* vp = Vst + (ks * 8 + q) * 72 + nd * 8 + g;
                bf[nd][0] = __float_as_uint(vp[0]);
                bf[nd][1] = __float_as_uint(vp[4 * 72]);
            }
            #pragma unroll
            for (int mi = 0; mi < 2; mi++)
                #pragma unroll
                for (int nd = 0; nd < 8; nd++)
                    mma_tf32(o[mi][nd], af[mi], bf[nd]);
        }
        __syncwarp();       // PV reads done before next chunk's P store
    }

    // ---- normalize + store ----
    #pragma unroll
    for (int mi = 0; mi < 2; mi++) {
        #pragma unroll
        for (int hh = 0; hh < 2; hh++) {
            float inv = 1.0f / lrow[mi][hh];
            int row = wm + mi * 16 + g + hh * 8;
            float* orow = O + ((size_t)bt * NF_ + row) * E_ + h * DH_;
            #pragma unroll
            for (int nd = 0; nd < 8; nd++) {
                float2 ov;
                ov.x = tf32r(o[mi][nd][hh * 2]     * inv);
                ov.y = tf32r(o[mi][nd][hh * 2 + 1] * inv);
                *(float2*)(orow + nd * 8 + 2 * q) = ov;
            }
        }
    }
}

// ---------------- host ----------------
extern "C" void kernel_launch(void* const* d_in, const int* in_sizes, int n_in,
                              void* d_out, int out_size)
{
    const float* inputs  = (const float*)d_in[0];
    const float* wq      = (const float*)d_in[1];
    const float* wk      = (const float*)d_in[2];
    const float* wv      = (const float*)d_in[3];
    const float* bq      = (const float*)d_in[4];
    const float* bk      = (const float*)d_in[5];
    const float* bv      = (const float*)d_in[6];
    const float* wo      = (const float*)d_in[7];
    const float* bo      = (const float*)d_in[8];
    const float* lnq_g   = (const float*)d_in[9];
    const float* lnq_b   = (const float*)d_in[10];
    const float* lnkv_g  = (const float*)d_in[11];
    const float* lnkv_b  = (const float*)d_in[12];
    const float* mlpq_w1 = (const float*)d_in[13];
    const float* mlpq_b1 = (const float*)d_in[14];
    const float* mlpq_w2 = (const float*)d_in[15];
    const float* mlpq_b2 = (const float*)d_in[16];
    const float* resln_g = (const float*)d_in[17];
    const float* resln_b = (const float*)d_in[18];
    const float* ln2_g   = (const float*)d_in[19];
    const float* ln2_b   = (const float*)d_in[20];
    const float* mlp_w1  = (const float*)d_in[21];
    const float* mlp_b1  = (const float*)d_in[22];
    const float* mlp_w2  = (const float*)d_in[23];
    const float* mlp_b2  = (const float*)d_in[24];
    float* out = (float*)d_out;

    float *qln, *q, *kvln, *kv, *t1, *t2, *hid, *wtA, *wtB, *wqT, *bkvC;
    cudaGetSymbolAddress((void**)&qln,  g_qln);
    cudaGetSymbolAddress((void**)&q,    g_q);
    cudaGetSymbolAddress((void**)&kvln, g_kvln);
    cudaGetSymbolAddress((void**)&kv,   g_kv);
    cudaGetSymbolAddress((void**)&t1,   g_t1);
    cudaGetSymbolAddress((void**)&t2,   g_t2);
    cudaGetSymbolAddress((void**)&hid,  g_hid);
    cudaGetSymbolAddress((void**)&wtA,  g_wtA);
    cudaGetSymbolAddress((void**)&wtB,  g_wtB);
    cudaGetSymbolAddress((void**)&wqT,  g_wqT);
    cudaGetSymbolAddress((void**)&bkvC, g_bkv);

    float* wkvT = wtA;                            // 1024 x 512 (wk rows 0-511, wv rows 512-1023)
    float* woT  = wtA + (size_t)2 * E_ * E_;
    float* mq1T = wtB;                            // (M, E)
    float* mq2T = wtB + (size_t)E_ * M_;          // (E, M)
    float* m1T  = wtB + (size_t)2 * E_ * M_;      // (M, E)
    float* m2T  = wtB + (size_t)3 * E_ * M_;      // (E, M)

    cudaFuncSetAttribute(tgemm2<false,false,false>, cudaFuncAttributeMaxDynamicSharedMemorySize, SMEM_TOTAL);
    cudaFuncSetAttribute(tgemm2<false,false,true >, cudaFuncAttributeMaxDynamicSharedMemorySize, SMEM_TOTAL);
    cudaFuncSetAttribute(tgemm2<true ,false,true >, cudaFuncAttributeMaxDynamicSharedMemorySize, SMEM_TOTAL);
    cudaFuncSetAttribute(tgemm2<false,true ,false>, cudaFuncAttributeMaxDynamicSharedMemorySize, SMEM_TOTAL);
    cudaFuncSetAttribute(attn_mma, cudaFuncAttributeMaxDynamicSharedMemorySize, ATTN_SMEM);

    // 0) weight transposes (+ tf32 rounding); wk & wv concatenated
    transpose_k<<<dim3(E_/32, E_/32), 256>>>(wq, wqT, E_, E_);
    transpose_k<<<dim3(E_/32, E_/32), 256>>>(wk, wkvT, E_, E_);
    transpose_k<<<dim3(E_/32, E_/32), 256>>>(wv, wkvT + (size_t)E_ * E_, E_, E_);
    transpose_k<<<dim3(E_/32, E_/32), 256>>>(wo, woT, E_, E_);
    transpose_k<<<dim3(M_/32, E_/32), 256>>>(mlpq_w1, mq1T, E_, M_);
    transpose_k<<<dim3(E_/32, M_/32), 256>>>(mlpq_w2, mq2T, M_, E_);
    transpose_k<<<dim3(M_/32, E_/32), 256>>>(mlp_w1,  m1T,  E_, M_);
    transpose_k<<<dim3(E_/32, M_/32), 256>>>(mlp_w2,  m2T,  M_, E_);
    concat_bias_k<<<4, 256>>>(bk, bv, bkvC);

    // 1) LayerNorms of the input (tf32-rounded outputs)
    ln_in_kernel<<<B_ * HW_ * NF_, 128>>>(inputs, lnq_g, lnq_b, lnkv_g, lnkv_b, qln, kvln);

    // 2) projections: q, and fused k|v (N=1024), tf32-rounded for attention mma
    tgemm2<false,false,true ><<<dim3(E_/128,   ROWS_Q/128),  128, SMEM_TOTAL>>>(qln,  wqT,  bq,   nullptr, q,  ROWS_Q,  E_,   E_);
    tgemm2<false,false,true ><<<dim3(1024/128, ROWS_KV/128), 128, SMEM_TOTAL>>>(kvln, wkvT, bkvC, nullptr, kv, ROWS_KV, 1024, E_);

    // 3) tensorized attention -> t1
    attn_mma<<<B_ * T_ * H_, 256, ATTN_SMEM>>>(q, kv, t1);

    // 4) out projection -> t2
    tgemm2<false,false,true ><<<dim3(E_/128, ROWS_KV/128), 128, SMEM_TOTAL>>>(t1, woT, bo, nullptr, t2, ROWS_KV, E_, E_);

    // 5) mlp_q: t2 -> hid (GELU, rounded) -> t1 (+ residual kvln)
    tgemm2<true ,false,true ><<<dim3(M_/128, ROWS_KV/128), 128, SMEM_TOTAL>>>(t2, mq1T, mlpq_b1, nullptr, hid, ROWS_KV, M_, E_);
    tgemm2<false,true ,false><<<dim3(E_/128, ROWS_KV/128), 128, SMEM_TOTAL>>>(hid, mq2T, mlpq_b2, kvln,  t1,  ROWS_KV, E_, M_);

    // 6) res_ln then ln_2 fused: t1 -> t2 (rounded)
    dual_ln_kernel<<<ROWS_KV, 128>>>(t1, resln_g, resln_b, ln2_g, ln2_b, t2);

    // 7) final MLP: t2 -> hid (GELU, rounded) -> out
    tgemm2<true ,false,true ><<<dim3(M_/128, ROWS_KV/128), 128, SMEM_TOTAL>>>(t2,  m1T, mlp_b1, nullptr, hid, ROWS_KV, M_, E_);
    tgemm2<false,false,false><<<dim3(E_/128, ROWS_KV/128), 128, SMEM_TOTAL>>>(hid, m2T, mlp_b2, nullptr, out, ROWS_KV, E_, M_);
}